// round 6
// baseline (speedup 1.0000x reference)
#include <cuda_runtime.h>
#include <cuda_fp16.h>
#include <cstdint>

#define BATCH 4
#define T 4096
#define D 1024
#define H 64
#define MTOT (BATCH * T)

// ---------------------------------------------------------------------------
// Packed split format (fp16): for each 64 source cols -> 128 packed cols:
//   cols [128c .. 128c+64)  = hi  (fp16 of value)
//   cols [128c+64 .. +128)  = lo  (fp16 of value - hi)
// GEMM term mapping (per source chunk):
//   NTERM=3: Ahi*Bhi + Ahi*Blo + Alo*Bhi   (near-exact)
//   NTERM=2: Ahi*Bhi + Alo*Bhi             (B truncated to fp16: ~2^-12 rel)
// ---------------------------------------------------------------------------
__device__ __align__(256) __half g_x2[(size_t)MTOT * 2 * D];        // 64 MB
__device__ __align__(256) __half g_wqk2[128 * 2 * D];               // 0.5 MB
__device__ __align__(256) __half g_wv2[(size_t)D * 2 * D];          // 4 MB
__device__ __align__(256) float  g_qk[(size_t)MTOT * 128];          // 8 MB
__device__ __align__(256) __half g_q2[(size_t)MTOT * 128];          // 4 MB
__device__ __align__(256) __half g_k2[(size_t)MTOT * 128];          // 4 MB
__device__ __align__(256) float  g_vt[(size_t)D * MTOT];            // 64 MB (V^T fp32)
__device__ __align__(256) __half g_vt2[(size_t)BATCH * D * 2 * T];  // 64 MB
__device__ __align__(256) float  g_S[(size_t)BATCH * T * T];        // 256 MB
__device__ __align__(256) __half g_p2[(size_t)BATCH * T * 2 * T];   // 256 MB

// ---------------------------------------------------------------------------
// Pack kernels
// ---------------------------------------------------------------------------
__global__ __launch_bounds__(256) void pack2(const float* __restrict__ src, int ldsrc,
                                             int col0, int ncols,
                                             __half* __restrict__ dst,
                                             float scale, int total) {
    int idx = blockIdx.x * 256 + threadIdx.x;
    if (idx >= total) return;
    int row = idx / ncols;
    int k = idx - row * ncols;
    float v = src[(size_t)row * ldsrc + col0 + k] * scale;
    __half hi = __float2half_rn(v);
    __half lo = __float2half_rn(v - __half2float(hi));
    size_t base = (size_t)row * (2 * ncols) + (size_t)(k >> 6) * 128 + (k & 63);
    dst[base] = hi;
    dst[base + 64] = lo;
}

// ---------------------------------------------------------------------------
// HMMA fp16 GEMM: C[M,N] = A'[M,*] * B'[N,*]^T on packed [hi|lo] operands.
// 128x128 CTA tile, 32 packed-K per iteration, term-mapped chunk addressing.
// 3-stage cp.async ring, one __syncthreads per iteration.
// CAUSAL: skip tiles bx > by.  KLIMIT: nc = 4*NTERM*(by+1).
// ---------------------------------------------------------------------------
#define ASTRIDE 80                          // bytes per 32-half smem row (64B + 16B pad)
#define TILE_BYTES (128 * ASTRIDE)          // 10240
#define STAGE_BYTES (2 * TILE_BYTES)        // A + B per stage
#define NSTAGE 3
#define SMEM_SZ (NSTAGE * STAGE_BYTES)      // 61440

__device__ __forceinline__ uint32_t smem_u32(const void* p) {
    uint32_t a;
    asm("{ .reg .u64 t; cvta.to.shared.u64 t, %1; cvt.u32.u64 %0, t; }" : "=r"(a) : "l"(p));
    return a;
}
__device__ __forceinline__ void cp16(uint32_t dst, const void* src) {
    asm volatile("cp.async.cg.shared.global [%0], [%1], 16;" :: "r"(dst), "l"(src));
}
__device__ __forceinline__ void ldm_x4(uint32_t* r, uint32_t addr) {
    asm volatile("ldmatrix.sync.aligned.m8n8.x4.shared.b16 {%0,%1,%2,%3}, [%4];"
                 : "=r"(r[0]), "=r"(r[1]), "=r"(r[2]), "=r"(r[3]) : "r"(addr));
}
__device__ __forceinline__ void mma16816(float* d, const uint32_t* a, const uint32_t* b) {
    asm volatile(
        "mma.sync.aligned.m16n8k16.row.col.f32.f16.f16.f32 "
        "{%0,%1,%2,%3}, {%4,%5,%6,%7}, {%8,%9}, {%0,%1,%2,%3};"
        : "+f"(d[0]), "+f"(d[1]), "+f"(d[2]), "+f"(d[3])
        : "r"(a[0]), "r"(a[1]), "r"(a[2]), "r"(a[3]), "r"(b[0]), "r"(b[1]));
}

// iteration kc (32 packed cols) -> element column offsets into A'/B'
template<int NTERM>
__device__ __forceinline__ void term_cols(int kc, int& acol, int& bcol) {
    int tt = kc >> 1, h = (kc & 1) * 32;
    int s, asub, bsub;
    if (NTERM == 3) { s = tt / 3; int j = tt - 3 * s; asub = (j == 2); bsub = (j == 1); }
    else            { s = tt >> 1; asub = tt & 1; bsub = 0; }
    acol = (2 * s + asub) * 64 + h;
    bcol = (2 * s + bsub) * 64 + h;
}

template<int NTERM, bool CAUSAL, bool KLIMIT>
__global__ __launch_bounds__(256)
void gemm_hmma(const __half* __restrict__ A, const __half* __restrict__ B,
               float* __restrict__ C, int lda, int ldb, int ldc, int NC,
               size_t sA, size_t sB, size_t sC) {
    const int bx = blockIdx.x, by = blockIdx.y, bz = blockIdx.z;
    if (CAUSAL && bx > by) return;
    A += (size_t)bz * sA;
    B += (size_t)bz * sB;
    C += (size_t)bz * sC;
    const int row0 = by * 128, col0 = bx * 128;
    const int nc = KLIMIT ? min(NC, 4 * NTERM * (by + 1)) : NC;

    extern __shared__ __align__(128) char smem[];
    const uint32_t sbase = smem_u32(smem);

    const int tid = threadIdx.x;
    const int lane = tid & 31;
    const int w = tid >> 5;
    const int wm = (w & 3) * 32;
    const int wn = (w >> 2) * 64;

    // cp.async mapping: thread -> (tile row, 32B half of the 64B row)
    const int lr = tid >> 1;
    const int lh = (tid & 1);
    const __half* Ap = A + (size_t)(row0 + lr) * lda + lh * 16;
    const __half* Bp = B + (size_t)(col0 + lr) * ldb + lh * 16;
    const uint32_t dstRow = lr * ASTRIDE + lh * 32;

    // ldmatrix addresses
    uint32_t aoff[2];
#pragma unroll
    for (int mt = 0; mt < 2; mt++)
        aoff[mt] = (uint32_t)((wm + mt * 16 + (lane & 15)) * ASTRIDE + ((lane >> 4) * 16));
    uint32_t boff[4];
#pragma unroll
    for (int nt2 = 0; nt2 < 4; nt2++)
        boff[nt2] = (uint32_t)((wn + nt2 * 16 + (lane & 7) + ((lane >> 4) & 1) * 8) * ASTRIDE
                               + (((lane >> 3) & 1) * 16));

    float acc[2][8][4];
#pragma unroll
    for (int mt = 0; mt < 2; mt++)
#pragma unroll
        for (int nt = 0; nt < 8; nt++)
#pragma unroll
            for (int q = 0; q < 4; q++) acc[mt][nt][q] = 0.f;

    // prologue: stages 0,1
#pragma unroll
    for (int p = 0; p < 2; p++) {
        if (p < nc) {
            int ac, bc; term_cols<NTERM>(p, ac, bc);
            uint32_t st = sbase + p * STAGE_BYTES;
            cp16(st + dstRow, Ap + ac);               cp16(st + dstRow + 16, Ap + ac + 8);
            cp16(st + TILE_BYTES + dstRow, Bp + bc);  cp16(st + TILE_BYTES + dstRow + 16, Bp + bc + 8);
        }
        asm volatile("cp.async.commit_group;" ::: "memory");
    }

    for (int kc = 0; kc < nc; kc++) {
        if (kc < nc - 1) { asm volatile("cp.async.wait_group 1;" ::: "memory"); }
        else             { asm volatile("cp.async.wait_group 0;" ::: "memory"); }
        __syncthreads();   // chunk kc visible to all; all warps done with chunk kc-1

        // prefetch kc+2 into ring slot (kc+2)%3 (slot consumed at kc-1)
        if (kc + 2 < nc) {
            int ac, bc; term_cols<NTERM>(kc + 2, ac, bc);
            uint32_t st = sbase + ((kc + 2) % NSTAGE) * STAGE_BYTES;
            cp16(st + dstRow, Ap + ac);               cp16(st + dstRow + 16, Ap + ac + 8);
            cp16(st + TILE_BYTES + dstRow, Bp + bc);  cp16(st + TILE_BYTES + dstRow + 16, Bp + bc + 8);
        }
        asm volatile("cp.async.commit_group;" ::: "memory");

        const uint32_t abase = sbase + (kc % NSTAGE) * STAGE_BYTES;
        const uint32_t bbase = abase + TILE_BYTES;
#pragma unroll
        for (int k16 = 0; k16 < 2; k16++) {
            const uint32_t ko = k16 * 32;
            uint32_t afr[2][4];
            ldm_x4(afr[0], abase + aoff[0] + ko);
            ldm_x4(afr[1], abase + aoff[1] + ko);
            uint32_t bfr[8][2];
#pragma unroll
            for (int nt2 = 0; nt2 < 4; nt2++) {
                uint32_t r[4];
                ldm_x4(r, bbase + boff[nt2] + ko);
                bfr[2 * nt2][0] = r[0];     bfr[2 * nt2][1] = r[1];
                bfr[2 * nt2 + 1][0] = r[2]; bfr[2 * nt2 + 1][1] = r[3];
            }
#pragma unroll
            for (int mt = 0; mt < 2; mt++)
#pragma unroll
                for (int nt = 0; nt < 8; nt++)
                    mma16816(acc[mt][nt], afr[mt], bfr[nt]);
        }
    }

    // epilogue
    const int rq = lane >> 2;
    const int cq = (lane & 3) * 2;
#pragma unroll
    for (int mt = 0; mt < 2; mt++) {
#pragma unroll
        for (int nt = 0; nt < 8; nt++) {
            float* p = C + (size_t)(row0 + wm + mt * 16 + rq) * ldc + col0 + wn + nt * 8 + cq;
            p[0] = acc[mt][nt][0];
            p[1] = acc[mt][nt][1];
            float* p2 = p + 8 * (size_t)ldc;
            p2[0] = acc[mt][nt][2];
            p2[1] = acc[mt][nt][3];
        }
    }
}

// ---------------------------------------------------------------------------
// Causal softmax: fp32 scores row -> split-fp16 P row ([hi|lo] per 64 cols)
// ---------------------------------------------------------------------------
__global__ __launch_bounds__(256)
void softmax_split(const float* __restrict__ S, __half* __restrict__ P) {
    const int i = blockIdx.x;
    const int b = blockIdx.y;
    const float* row = S + ((size_t)b * T + i) * (size_t)T;
    __half* prow = P + ((size_t)b * T + i) * (size_t)(2 * T);
    const int tid = threadIdx.x;
    const int len = i + 1;

    constexpr int R = T / 256;
    float local[R];
    float m = -3.4e38f;
#pragma unroll
    for (int r = 0; r < R; r++) {
        int j = r * 256 + tid;
        float v = (j < len) ? row[j] : -3.4e38f;
        local[r] = v;
        m = fmaxf(m, v);
    }
    __shared__ float red[8];
#pragma unroll
    for (int o = 16; o; o >>= 1) m = fmaxf(m, __shfl_xor_sync(0xffffffffu, m, o));
    if ((tid & 31) == 0) red[tid >> 5] = m;
    __syncthreads();
    m = red[0];
#pragma unroll
    for (int w = 1; w < 8; w++) m = fmaxf(m, red[w]);
    __syncthreads();

    float s = 0.f;
#pragma unroll
    for (int r = 0; r < R; r++) {
        int j = r * 256 + tid;
        float e = (j < len) ? __expf(local[r] - m) : 0.f;
        local[r] = e;
        s += e;
    }
#pragma unroll
    for (int o = 16; o; o >>= 1) s += __shfl_xor_sync(0xffffffffu, s, o);
    if ((tid & 31) == 0) red[tid >> 5] = s;
    __syncthreads();
    s = red[0];
#pragma unroll
    for (int w = 1; w < 8; w++) s += red[w];

    const float inv = 1.f / s;
#pragma unroll
    for (int r = 0; r < R; r++) {
        int j = r * 256 + tid;
        float p = local[r] * inv;
        __half hi = __float2half_rn(p);
        __half lo = __float2half_rn(p - __half2float(hi));
        size_t base = (size_t)(j >> 6) * 128 + (j & 63);
        prow[base] = hi;
        prow[base + 64] = lo;
    }
}

// ---------------------------------------------------------------------------
// kernel_launch
// ---------------------------------------------------------------------------
extern "C" void kernel_launch(void* const* d_in, const int* in_sizes, int n_in,
                              void* d_out, int out_size) {
    const float* x  = (const float*)d_in[0];
    const float* Wk = (const float*)d_in[1];
    const float* Wq = (const float*)d_in[2];
    const float* Wv = (const float*)d_in[3];
    float* out = (float*)d_out;

    __half *x2, *wqk2, *wv2, *q2, *k2, *vt2, *p2;
    float *qk, *vt, *S;
    cudaGetSymbolAddress((void**)&x2, g_x2);
    cudaGetSymbolAddress((void**)&wqk2, g_wqk2);
    cudaGetSymbolAddress((void**)&wv2, g_wv2);
    cudaGetSymbolAddress((void**)&qk, g_qk);
    cudaGetSymbolAddress((void**)&q2, g_q2);
    cudaGetSymbolAddress((void**)&k2, g_k2);
    cudaGetSymbolAddress((void**)&vt, g_vt);
    cudaGetSymbolAddress((void**)&vt2, g_vt2);
    cudaGetSymbolAddress((void**)&S, g_S);
    cudaGetSymbolAddress((void**)&p2, g_p2);

    cudaFuncSetAttribute(gemm_hmma<3, false, false>, cudaFuncAttributeMaxDynamicSharedMemorySize, SMEM_SZ);
    cudaFuncSetAttribute(gemm_hmma<2, false, false>, cudaFuncAttributeMaxDynamicSharedMemorySize, SMEM_SZ);
    cudaFuncSetAttribute(gemm_hmma<3, true,  false>, cudaFuncAttributeMaxDynamicSharedMemorySize, SMEM_SZ);
    cudaFuncSetAttribute(gemm_hmma<2, false, true >, cudaFuncAttributeMaxDynamicSharedMemorySize, SMEM_SZ);

    // 1) input packs (single [hi|lo] format serves A- and B-roles)
    pack2<<<(MTOT * D + 255) / 256, 256>>>(x, D, 0, D, x2, 1.f, MTOT * D);
    pack2<<<(64 * D + 255) / 256, 256>>>(Wq, D, 0, D, wqk2, 1.f, 64 * D);
    pack2<<<(64 * D + 255) / 256, 256>>>(Wk, D, 0, D, wqk2 + (size_t)64 * 2 * D, 1.f, 64 * D);
    pack2<<<(D * D + 255) / 256, 256>>>(Wv, D, 0, D, wv2, 1.f, D * D);

    // 2) QK projection (3-term, near-exact): x2[16384,*] x wqk2[128,*]^T -> qk fp32
    gemm_hmma<3, false, false><<<dim3(1, MTOT / 128, 1), 256, SMEM_SZ>>>(
        x2, wqk2, qk, 2 * D, 2 * D, 128, 96, 0, 0, 0);

    // 3) V^T projection (2-term): wv2[1024,*] x x2[16384,*]^T -> vt fp32 [1024,16384]
    gemm_hmma<2, false, false><<<dim3(MTOT / 128, D / 128, 1), 256, SMEM_SZ>>>(
        wv2, x2, vt, 2 * D, 2 * D, MTOT, 64, 0, 0, 0);

    // 4) split-pack Q (pre-scaled 1/8), K, V^T
    pack2<<<(MTOT * 64 + 255) / 256, 256>>>(qk, 128, 0, 64, q2, 0.125f, MTOT * 64);
    pack2<<<(MTOT * 64 + 255) / 256, 256>>>(qk, 128, 64, 64, k2, 1.f, MTOT * 64);
    for (int b = 0; b < BATCH; b++) {
        pack2<<<(D * T + 255) / 256, 256>>>(
            vt, MTOT, b * T, T, vt2 + (size_t)b * D * 2 * T, 1.f, D * T);
    }

    // 5) scores (3-term, causal tile skip): S[b] = Qs K^T
    gemm_hmma<3, true, false><<<dim3(T / 128, T / 128, BATCH), 256, SMEM_SZ>>>(
        q2, k2, S, 128, 128, T, 6,
        (size_t)T * 128, (size_t)T * 128, (size_t)T * T);

    // 6) softmax -> split P
    softmax_split<<<dim3(T, BATCH), 256>>>(S, p2);

    // 7) out[b] = P[b] @ V[b] (2-term, causal K-limit)
    gemm_hmma<2, false, true><<<dim3(D / 128, T / 128, BATCH), 256, SMEM_SZ>>>(
        p2, vt2, out, 2 * T, 2 * T, D, 256,
        (size_t)T * 2 * T, (size_t)D * 2 * T, (size_t)T * D);
}